// round 16
// baseline (speedup 1.0000x reference)
#include <cuda_runtime.h>
#include <cuda_fp16.h>

#define NN 100000
#define NE 800000
#define TOT (7 * NN)          // (relation, dst) counters
#define SCAN_NB ((TOT + 1023) / 1024)

// ---------------- scratch (static __device__ globals; no allocs) ----------------
__device__ __align__(16) __half g_msg2h[7 * NN * 32];  // 44.8 MB fp16 messages (fully overwritten)
__device__ __align__(16) __half g_msg1h[2 * NN * 16];  // 6.4 MB fp16 messages
__device__ __align__(16) float g_msg0[2 * NN * 8];     // padded rows: 6 used + 2 pad
__device__ __align__(16) float g_xp  [NN * 8];         // padded x copy (6 used + 2 zero)
__device__ __align__(16) int   g_hist[TOT];            // edge counts per (r,dst) — also mean cnt
__device__ __align__(16) int   g_offs[TOT];            // segment starts
__device__ __align__(16) int   g_cur [TOT];            // working cursors
__device__ __align__(16) int   g_bsum[SCAN_NB];        // scan block sums
__device__ __align__(16) unsigned g_ebuf[7 * NE];      // dst-sorted src indices
__device__ __align__(16) float g_h0  [NN * 16];
__device__ __align__(16) __half g_h0h[NN * 16];
__device__ __align__(16) float g_h1  [NN * 32];
__device__ __align__(16) __half g_h1h[NN * 32];
__device__ __align__(16) float g_Wc0[3 * 6 * 16];
__device__ __align__(16) float g_Wc1[3 * 16 * 32];
__device__ __align__(16) float g_W2hi[8 * 64 * 32];    // [ch][n][k], tf32-exact
__device__ __align__(16) float g_W2lo[8 * 64 * 32];
__device__ __align__(16) float g_bc0[16];
__device__ __align__(16) float g_bc1[32];
__device__ __align__(16) float g_bc2[64];

// ---------------- helpers ----------------
__device__ __forceinline__ void red_add_v4(float* a, float4 v) {
    asm volatile("red.global.add.v4.f32 [%0], {%1,%2,%3,%4};"
                 :: "l"(a), "f"(v.x), "f"(v.y), "f"(v.z), "f"(v.w) : "memory");
}
__device__ __forceinline__ void red_add_v4h(__half* a, float4 bits) {
    asm volatile("red.global.add.noftz.v4.f16x2 [%0], {%1,%2,%3,%4};"
                 :: "l"(a), "r"(__float_as_uint(bits.x)), "r"(__float_as_uint(bits.y)),
                    "r"(__float_as_uint(bits.z)), "r"(__float_as_uint(bits.w)) : "memory");
}
__device__ __forceinline__ unsigned tf32_of(float f) {
    unsigned r;
    asm("cvt.rna.tf32.f32 %0, %1;" : "=r"(r) : "f"(f));
    return r;
}
__device__ __forceinline__ void mma_tf32(float* d, unsigned a0, unsigned a1,
                                         unsigned a2, unsigned a3,
                                         unsigned b0, unsigned b1) {
    asm("mma.sync.aligned.m16n8k8.row.col.f32.tf32.tf32.f32 "
        "{%0,%1,%2,%3}, {%4,%5,%6,%7}, {%8,%9}, {%0,%1,%2,%3};"
        : "+f"(d[0]), "+f"(d[1]), "+f"(d[2]), "+f"(d[3])
        : "r"(a0), "r"(a1), "r"(a2), "r"(a3), "r"(b0), "r"(b1));
}

struct ESet { const int* e[7]; };

// ---------------- zero scratch + fold weights + pad x ----------------
__global__ void k_zero_prep(const float* __restrict__ x,
                            const float* __restrict__ W0n, const float* __restrict__ W0r,
                            const float* __restrict__ b0,
                            const float* __restrict__ W1n, const float* __restrict__ W1r,
                            const float* __restrict__ b1,  const float* __restrict__ P1,
                            const float* __restrict__ pb1,
                            const float* __restrict__ W2n, const float* __restrict__ W2r,
                            const float* __restrict__ b2,  const float* __restrict__ P2,
                            const float* __restrict__ pb2) {
    int i = blockIdx.x * blockDim.x + threadIdx.x;
    int stride = gridDim.x * blockDim.x;
    if (i < 192) g_Wc0[i] = W0n[i];
    if (i < 96)  g_Wc0[192 + i] = W0r[i] + W0r[96 + i];
    if (i < 16)  g_bc0[i] = b0[i] + b0[16 + i];
    if (i < 1024) g_Wc1[i] = W1n[i];
    if (i < 512)  g_Wc1[1024 + i] = W1r[i] + W1r[512 + i] + P1[i];
    if (i < 32)   g_bc1[i] = b1[i] + b1[32 + i] + pb1[i];
    if (i < 16384) {
        int ch = i >> 11, j = i & 2047;
        int k = j >> 6, n = j & 63;
        float w;
        if (ch < 7) w = W2n[i];
        else {
            w = P2[j];
            for (int r = 0; r < 7; r++) w += W2r[r * 2048 + j];
        }
        unsigned hi = tf32_of(w);
        unsigned lo = tf32_of(w - __uint_as_float(hi));
        int o = ch * 2048 + n * 32 + k;
        g_W2hi[o] = __uint_as_float(hi);
        g_W2lo[o] = __uint_as_float(lo);
    }
    if (i < 64) {
        float s = pb2[i];
        for (int r = 0; r < 7; r++) s += b2[r * 64 + i];
        g_bc2[i] = s;
    }
    for (int t = i; t < NN * 8; t += stride) {
        int node = t >> 3, c = t & 7;
        g_xp[t] = (c < 6) ? __ldg(x + node * 6 + c) : 0.f;
    }
    for (int t = i; t < TOT; t += stride) g_hist[t] = 0;
    float4 z = make_float4(0.f, 0.f, 0.f, 0.f);
    float4* a1 = reinterpret_cast<float4*>(g_msg1h);
    for (int t = i; t < 2 * NN * 16 / 8; t += stride) a1[t] = z;
    float4* a0 = reinterpret_cast<float4*>(g_msg0);
    for (int t = i; t < 2 * NN * 8 / 4; t += stride) a0[t] = z;
}

// ---------------- layer-2 binning: histogram ----------------
__global__ void __launch_bounds__(256)
k_hist(ESet es) {
    int e = blockIdx.x * 256 + threadIdx.x;
    int r = blockIdx.y;
    int dst = __ldg(es.e[r] + NE + e);
    atomicAdd(g_hist + r * NN + dst, 1);
}

// ---------------- scan pass 1: per-1024-block exclusive scan + block sums ----------------
__global__ void __launch_bounds__(256)
k_scan1() {
    __shared__ int sA[256], sB[256];
    int tid = threadIdx.x, bid = blockIdx.x;
    int base = bid * 1024 + tid * 4;
    int v[4], s = 0;
#pragma unroll
    for (int i = 0; i < 4; i++) {
        v[i] = (base + i < TOT) ? g_hist[base + i] : 0;
        s += v[i];
    }
    sA[tid] = s;
    __syncthreads();
    int* sp = sA; int* dp = sB;
    for (int off = 1; off < 256; off <<= 1) {
        dp[tid] = sp[tid] + ((tid >= off) ? sp[tid - off] : 0);
        __syncthreads();
        int* tmp = sp; sp = dp; dp = tmp;
    }
    int run = sp[tid] - s;   // exclusive prefix of this thread's chunk
#pragma unroll
    for (int i = 0; i < 4; i++) {
        if (base + i < TOT) g_offs[base + i] = run;
        run += v[i];
    }
    if (tid == 255) g_bsum[bid] = sp[255];
}

// ---------------- scan pass 2: sequential scan of block sums ----------------
__global__ void k_scan2() {
    if (threadIdx.x == 0 && blockIdx.x == 0) {
        int run = 0;
        for (int i = 0; i < SCAN_NB; i++) {
            int t = g_bsum[i];
            g_bsum[i] = run;
            run += t;
        }
    }
}

// ---------------- scan pass 3: add block bases, init cursors ----------------
__global__ void __launch_bounds__(256)
k_scan3() {
    int tid = threadIdx.x, bid = blockIdx.x;
    int b = g_bsum[bid];
    int base = bid * 1024 + tid * 4;
#pragma unroll
    for (int i = 0; i < 4; i++) {
        int g = base + i;
        if (g < TOT) {
            int o = g_offs[g] + b;
            g_offs[g] = o;
            g_cur[g] = o;
        }
    }
}

// ---------------- reorder: write src into dst-sorted slots ----------------
__global__ void __launch_bounds__(256)
k_reorder(ESet es) {
    int e = blockIdx.x * 256 + threadIdx.x;
    int r = blockIdx.y;
    const int* ei = es.e[r];
    int src = __ldg(ei + e);
    int dst = __ldg(ei + NE + e);
    int pos = atomicAdd(g_cur + r * NN + dst, 1);
    g_ebuf[pos] = (unsigned)src;
}

// ---------------- accumulate: warp per (dst, relation), register f32 reduce ----------------
// grid (NN/8, 7), block 256 (8 warps). Writes every msg2h row (zeros if no edges).
__global__ void __launch_bounds__(256)
k_accum(const __half* __restrict__ feat, __half* __restrict__ msg) {
    int tid  = threadIdx.x;
    int lane = tid & 31;
    int dst  = blockIdx.x * 8 + (tid >> 5);
    int r    = blockIdx.y;
    int g    = r * NN + dst;
    int start = __ldg(g_offs + g);
    int n     = __ldg(g_hist + g);
    int sub = lane >> 2;   // edge slot 0..7
    int c   = lane & 3;    // 16B chunk 0..3

    float acc[8];
#pragma unroll
    for (int i = 0; i < 8; i++) acc[i] = 0.f;

    for (int it = 0; it < n; it += 8) {
        int ei = it + sub;
        if (ei < n) {
            unsigned src = __ldg(g_ebuf + start + ei);
            float4 v = __ldg(reinterpret_cast<const float4*>(feat + (size_t)src * 32) + c);
            const __half2* hp = reinterpret_cast<const __half2*>(&v);
#pragma unroll
            for (int q = 0; q < 4; q++) {
                float2 f2 = __half22float2(hp[q]);
                acc[2 * q]     += f2.x;
                acc[2 * q + 1] += f2.y;
            }
        }
    }
    // reduce across the 8 edge slots (lane bits 2..4)
#pragma unroll
    for (int i = 0; i < 8; i++) {
        acc[i] += __shfl_xor_sync(0xffffffffu, acc[i], 4);
        acc[i] += __shfl_xor_sync(0xffffffffu, acc[i], 8);
        acc[i] += __shfl_xor_sync(0xffffffffu, acc[i], 16);
    }
    if (sub == 0) {
        __half2 h0 = __floats2half2_rn(acc[0], acc[1]);
        __half2 h1 = __floats2half2_rn(acc[2], acc[3]);
        __half2 h2 = __floats2half2_rn(acc[4], acc[5]);
        __half2 h3 = __floats2half2_rn(acc[6], acc[7]);
        uint4 o;
        o.x = *reinterpret_cast<unsigned*>(&h0);
        o.y = *reinterpret_cast<unsigned*>(&h1);
        o.z = *reinterpret_cast<unsigned*>(&h2);
        o.w = *reinterpret_cast<unsigned*>(&h3);
        *reinterpret_cast<uint4*>(msg + (size_t)g * 32 + 8 * c) = o;
    }
}

// ---------------- scatter layer 1: fp16 warp-coop (R14) ----------------
__global__ void __launch_bounds__(256)
k_scatter16h(ESet es, const __half* __restrict__ feat, __half* __restrict__ msg) {
    int lane = threadIdx.x & 31;
    int warp = (blockIdx.x * 256 + threadIdx.x) >> 5;
    int e = warp * 32 + lane;
    int r = blockIdx.y;
    const int* ei = es.e[r];
    int src = __ldg(ei + e);
    int dst = __ldg(ei + NE + e);
    int sub = lane >> 1;
    int c   = lane & 1;
#pragma unroll
    for (int j = 0; j < 2; j++) {
        int el = j * 16 + sub;
        int s = __shfl_sync(0xffffffffu, src, el);
        int d = __shfl_sync(0xffffffffu, dst, el);
        float4 v = __ldg(reinterpret_cast<const float4*>(feat + (size_t)s * 16) + c);
        red_add_v4h(msg + ((size_t)r * NN + d) * 16 + 8 * c, v);
    }
}

// ---------------- scatter layer 0: f32 padded rows, warp-coop (R14) ----------------
__global__ void __launch_bounds__(256)
k_scatter6p(ESet es, const float* __restrict__ xp, float* __restrict__ msg) {
    int lane = threadIdx.x & 31;
    int warp = (blockIdx.x * 256 + threadIdx.x) >> 5;
    int e = warp * 32 + lane;
    int r = blockIdx.y;
    const int* ei = es.e[r];
    int src = __ldg(ei + e);
    int dst = __ldg(ei + NE + e);
    int sub = lane >> 1;
    int c   = lane & 1;
#pragma unroll
    for (int j = 0; j < 2; j++) {
        int el = j * 16 + sub;
        int s = __shfl_sync(0xffffffffu, src, el);
        int d = __shfl_sync(0xffffffffu, dst, el);
        float4 v = __ldg(reinterpret_cast<const float4*>(xp + (size_t)s * 8) + c);
        red_add_v4(msg + ((size_t)r * NN + d) * 8 + 4 * c, v);
    }
}

// ---------------- layer-0 GEMM (R14) ----------------
__global__ void __launch_bounds__(256)
k_gemm0(const float* __restrict__ msg0, const float* __restrict__ xp,
        const float* __restrict__ Wcat, const float* __restrict__ bias,
        float* __restrict__ out, __half* __restrict__ hout) {
    constexpr int OUT = 16, LDT = 9;
    __shared__ __align__(16) float shW[6 * OUT];
    __shared__ float shT[256 * LDT];
    int tid  = threadIdx.x;
    int base = blockIdx.x * 256;
    int node = base + tid;
    const float* chp[3] = { msg0, msg0 + (size_t)NN * 8, xp };

    float acc[OUT];
#pragma unroll
    for (int j = 0; j < OUT; j++) acc[j] = __ldg(bias + j);

    float4 pre[2];
    {
        const float4* m4 = reinterpret_cast<const float4*>(chp[0]);
#pragma unroll
        for (int j = 0; j < 2; j++) {
            int f = j * 256 + tid;
            int g = base * 2 + f;
            pre[j] = __ldg(m4 + (g < NN * 2 ? g : NN * 2 - 1));
        }
    }

    for (int ch = 0; ch < 3; ch++) {
        __syncthreads();
#pragma unroll
        for (int j = 0; j < 2; j++) {
            int f = j * 256 + tid;
            int nl = f >> 1, c = f & 1;
            float4 v = pre[j];
            float* t = shT + nl * LDT + 4 * c;
            t[0] = v.x; t[1] = v.y; t[2] = v.z; t[3] = v.w;
        }
        if (tid < 96) shW[tid] = __ldg(Wcat + ch * 96 + tid);
        __syncthreads();

        if (ch + 1 < 3) {
            const float4* m4 = reinterpret_cast<const float4*>(chp[ch + 1]);
#pragma unroll
            for (int j = 0; j < 2; j++) {
                int f = j * 256 + tid;
                int g = base * 2 + f;
                pre[j] = __ldg(m4 + (g < NN * 2 ? g : NN * 2 - 1));
            }
        }

#pragma unroll
        for (int k = 0; k < 6; k++) {
            float m = shT[tid * LDT + k];
            const float4* w4 = reinterpret_cast<const float4*>(shW + k * OUT);
#pragma unroll
            for (int j = 0; j < OUT / 4; j++) {
                float4 w = w4[j];
                acc[4 * j + 0] += m * w.x;
                acc[4 * j + 1] += m * w.y;
                acc[4 * j + 2] += m * w.z;
                acc[4 * j + 3] += m * w.w;
            }
        }
    }

    if (node < NN) {
        float4* o4 = reinterpret_cast<float4*>(out + (size_t)node * OUT);
        __half2* h2 = reinterpret_cast<__half2*>(hout + (size_t)node * OUT);
#pragma unroll
        for (int j = 0; j < OUT / 4; j++) {
            float4 v;
            v.x = acc[4 * j + 0]; v.y = acc[4 * j + 1];
            v.z = acc[4 * j + 2]; v.w = acc[4 * j + 3];
            o4[j] = v;
            h2[2 * j]     = __floats2half2_rn(v.x, v.y);
            h2[2 * j + 1] = __floats2half2_rn(v.z, v.w);
        }
    }
}

// ---------------- layer-1 GEMM (R12-proven) ----------------
__global__ void __launch_bounds__(256)
k_gemm1(const __half* __restrict__ msgh, const float* __restrict__ h0,
        const float* __restrict__ Wcat, const float* __restrict__ bias,
        float* __restrict__ out, __half* __restrict__ hout) {
    constexpr int CHUNK = 16, OUT = 32, LDT = CHUNK + 1;
    __shared__ __align__(16) float shW[CHUNK * OUT];
    __shared__ float shT[256 * LDT];
    int tid  = threadIdx.x;
    int base = blockIdx.x * 256;
    int node = base + tid;

    float acc[OUT];
#pragma unroll
    for (int j = 0; j < OUT; j++) acc[j] = __ldg(bias + j);

    float4 pre[4];
    float4 preW[2];
    {
        const float4* src4 = reinterpret_cast<const float4*>(msgh);
#pragma unroll
        for (int j = 0; j < 2; j++) {
            int f = j * 256 + tid;
            int g = base * 2 + f;
            pre[j] = __ldg(src4 + (g < NN * 2 ? g : NN * 2 - 1));
        }
        const float4* w4 = reinterpret_cast<const float4*>(Wcat);
#pragma unroll
        for (int j = 0; j < 2; j++) {
            int f = j * 256 + tid;
            preW[j] = (f < 128) ? __ldg(w4 + f) : make_float4(0.f, 0.f, 0.f, 0.f);
        }
    }

    for (int ch = 0; ch < 3; ch++) {
        __syncthreads();
        if (ch < 2) {
#pragma unroll
            for (int j = 0; j < 2; j++) {
                int f = j * 256 + tid;
                int nl = f >> 1, c = f & 1;
                const __half2* hp = reinterpret_cast<const __half2*>(&pre[j]);
                float* t = shT + nl * LDT + 8 * c;
#pragma unroll
                for (int q = 0; q < 4; q++) {
                    float2 f2 = __half22float2(hp[q]);
                    t[2 * q]     = f2.x;
                    t[2 * q + 1] = f2.y;
                }
            }
        } else {
#pragma unroll
            for (int j = 0; j < 4; j++) {
                int f = j * 256 + tid;
                int nl = f >> 2, c = f & 3;
                float4 v = pre[j];
                float* t = shT + nl * LDT + 4 * c;
                t[0] = v.x; t[1] = v.y; t[2] = v.z; t[3] = v.w;
            }
        }
#pragma unroll
        for (int j = 0; j < 2; j++) {
            int f = j * 256 + tid;
            if (f < 128) reinterpret_cast<float4*>(shW)[f] = preW[j];
        }
        __syncthreads();

        if (ch + 1 < 3) {
            if (ch + 1 < 2) {
                const float4* src4 = reinterpret_cast<const float4*>(msgh + (size_t)NN * 16);
#pragma unroll
                for (int j = 0; j < 2; j++) {
                    int f = j * 256 + tid;
                    int g = base * 2 + f;
                    pre[j] = __ldg(src4 + (g < NN * 2 ? g : NN * 2 - 1));
                }
            } else {
                const float4* src4 = reinterpret_cast<const float4*>(h0);
#pragma unroll
                for (int j = 0; j < 4; j++) {
                    int f = j * 256 + tid;
                    int g = base * 4 + f;
                    pre[j] = __ldg(src4 + (g < NN * 4 ? g : NN * 4 - 1));
                }
            }
            const float4* w4 = reinterpret_cast<const float4*>(Wcat + (ch + 1) * CHUNK * OUT);
#pragma unroll
            for (int j = 0; j < 2; j++) {
                int f = j * 256 + tid;
                preW[j] = (f < 128) ? __ldg(w4 + f) : make_float4(0.f, 0.f, 0.f, 0.f);
            }
        }

#pragma unroll 8
        for (int k = 0; k < CHUNK; k++) {
            float m = shT[tid * LDT + k];
            const float4* w4 = reinterpret_cast<const float4*>(shW + k * OUT);
#pragma unroll
            for (int j = 0; j < OUT / 4; j++) {
                float4 w = w4[j];
                acc[4 * j + 0] += m * w.x;
                acc[4 * j + 1] += m * w.y;
                acc[4 * j + 2] += m * w.z;
                acc[4 * j + 3] += m * w.w;
            }
        }
    }

    if (node < NN) {
        float4* o4 = reinterpret_cast<float4*>(out + (size_t)node * OUT);
        __half2* h2 = reinterpret_cast<__half2*>(hout + (size_t)node * OUT);
#pragma unroll
        for (int j = 0; j < OUT / 4; j++) {
            float4 v;
            v.x = fmaxf(acc[4 * j + 0], 0.f);
            v.y = fmaxf(acc[4 * j + 1], 0.f);
            v.z = fmaxf(acc[4 * j + 2], 0.f);
            v.w = fmaxf(acc[4 * j + 3], 0.f);
            o4[j] = v;
            h2[2 * j]     = __floats2half2_rn(v.x, v.y);
            h2[2 * j + 1] = __floats2half2_rn(v.z, v.w);
        }
    }
}

// ---------------- layer-2 GEMM: split-tf32 mma.sync; counts from hist ----------------
__global__ void __launch_bounds__(256)
k_gemm2_tc(const __half* __restrict__ msgh, const float* __restrict__ h1,
           const int* __restrict__ hist,
           const float* __restrict__ Whi, const float* __restrict__ Wlo,
           const float* __restrict__ bias, float* __restrict__ out) {
    __shared__ float shA [128 * 36];
    __shared__ float shWh[64 * 36];
    __shared__ float shWl[64 * 36];
    __shared__ float shSc[3][128];
    __shared__ float shB[64];
    int tid  = threadIdx.x;
    int lane = tid & 31;
    int w    = tid >> 5;
    int base = blockIdx.x * 128;

    if (tid < 64) shB[tid] = __ldg(bias + tid);
    if (tid < 128) {
        int node = base + tid;
        const int mc[3] = {2, 3, 6};
#pragma unroll
        for (int m = 0; m < 3; m++) {
            float c = (node < NN) ? (float)__ldg(hist + mc[m] * NN + node) : 1.f;
            shSc[m][tid] = 1.f / fmaxf(c, 1.f);
        }
    }

    float d[8][4];
#pragma unroll
    for (int nt = 0; nt < 8; nt++)
#pragma unroll
        for (int j = 0; j < 4; j++) d[nt][j] = 0.f;

    float4 pre[4];
    float4 preW[4];
    {
        const float4* src4 = reinterpret_cast<const float4*>(msgh);
#pragma unroll
        for (int j = 0; j < 2; j++) {
            int f = j * 256 + tid;
            int g = base * 4 + f;
            pre[j] = __ldg(src4 + (g < NN * 4 ? g : NN * 4 - 1));
        }
        const float4* wh4 = reinterpret_cast<const float4*>(Whi);
        const float4* wl4 = reinterpret_cast<const float4*>(Wlo);
#pragma unroll
        for (int j = 0; j < 2; j++) preW[j]     = __ldg(wh4 + j * 256 + tid);
#pragma unroll
        for (int j = 0; j < 2; j++) preW[2 + j] = __ldg(wl4 + j * 256 + tid);
    }

    int rl1 = 16 * w + (lane >> 2);
    int rl2 = rl1 + 8;
    int kc  = lane & 3;
    int nb  = lane >> 2;

    for (int ch = 0; ch < 8; ch++) {
        __syncthreads();
        int msel = (ch == 2) ? 0 : (ch == 3) ? 1 : (ch == 6) ? 2 : -1;
        if (ch < 7) {
#pragma unroll
            for (int j = 0; j < 2; j++) {
                int f = j * 256 + tid;
                int nl = f >> 2, c4 = f & 3;
                const __half2* hp = reinterpret_cast<const __half2*>(&pre[j]);
                float sc = (msel >= 0) ? shSc[msel][nl] : 1.f;
                float* t = shA + nl * 36 + 8 * c4;
#pragma unroll
                for (int q = 0; q < 4; q++) {
                    float2 f2 = __half22float2(hp[q]);
                    t[2 * q]     = f2.x * sc;
                    t[2 * q + 1] = f2.y * sc;
                }
            }
        } else {
#pragma unroll
            for (int j = 0; j < 4; j++) {
                int f = j * 256 + tid;
                int nl = f >> 3, c4 = f & 7;
                float4 v = pre[j];
                float* t = shA + nl * 36 + 4 * c4;
                t[0] = v.x; t[1] = v.y; t[2] = v.z; t[3] = v.w;
            }
        }
#pragma unroll
        for (int j = 0; j < 2; j++) {
            int f = j * 256 + tid;
            int n = f >> 3, k4 = f & 7;
            float4 vh = preW[j], vl = preW[2 + j];
            float* th = shWh + n * 36 + 4 * k4;
            float* tl = shWl + n * 36 + 4 * k4;
            th[0] = vh.x; th[1] = vh.y; th[2] = vh.z; th[3] = vh.w;
            tl[0] = vl.x; tl[1] = vl.y; tl[2] = vl.z; tl[3] = vl.w;
        }
        __syncthreads();

        if (ch + 1 < 8) {
            if (ch + 1 < 7) {
                const float4* src4 = reinterpret_cast<const float4*>(msgh + (size_t)(ch + 1) * NN * 32);
#pragma unroll
                for (int j = 0; j < 2; j++) {
                    int f = j * 256 + tid;
                    int g = base * 4 + f;
                    pre[j] = __ldg(src4 + (g < NN * 4 ? g : NN * 4 - 1));
                }
            } else {
                const float4* src4 = reinterpret_cast<const float4*>(h1);
#pragma unroll
                for (int j = 0; j < 4; j++) {
                    int f = j * 256 + tid;
                    int g = base * 8 + f;
                    pre[j] = __ldg(src4 + (g < NN * 8 ? g : NN * 8 - 1));
                }
            }
            const float4* wh4 = reinterpret_cast<const float4*>(Whi + (ch + 1) * 2048);
            const float4* wl4 = reinterpret_cast<const float4*>(Wlo + (ch + 1) * 2048);
#pragma unroll
            for (int j = 0; j < 2; j++) preW[j]     = __ldg(wh4 + j * 256 + tid);
#pragma unroll
            for (int j = 0; j < 2; j++) preW[2 + j] = __ldg(wl4 + j * 256 + tid);
        }

        bool needLo = (msel >= 0) || (ch == 7);
#pragma unroll
        for (int k0 = 0; k0 < 32; k0 += 8) {
            int c = k0 + kc;
            float a0f = shA[rl1 * 36 + c];
            float a1f = shA[rl2 * 36 + c];
            float a2f = shA[rl1 * 36 + c + 4];
            float a3f = shA[rl2 * 36 + c + 4];
            unsigned ah0 = tf32_of(a0f), ah1 = tf32_of(a1f);
            unsigned ah2 = tf32_of(a2f), ah3 = tf32_of(a3f);
            unsigned al0 = 0, al1 = 0, al2 = 0, al3 = 0;
            if (needLo) {
                al0 = tf32_of(a0f - __uint_as_float(ah0));
                al1 = tf32_of(a1f - __uint_as_float(ah1));
                al2 = tf32_of(a2f - __uint_as_float(ah2));
                al3 = tf32_of(a3f - __uint_as_float(ah3));
            }
#pragma unroll
            for (int nt = 0; nt < 8; nt++) {
                int wr = (nt * 8 + nb) * 36 + k0 + kc;
                unsigned bh0 = __float_as_uint(shWh[wr]);
                unsigned bh1 = __float_as_uint(shWh[wr + 4]);
                unsigned bl0 = __float_as_uint(shWl[wr]);
                unsigned bl1 = __float_as_uint(shWl[wr + 4]);
                mma_tf32(d[nt], ah0, ah1, ah2, ah3, bh0, bh1);
                mma_tf32(d[nt], ah0, ah1, ah2, ah3, bl0, bl1);
                if (needLo) mma_tf32(d[nt], al0, al1, al2, al3, bh0, bh1);
            }
        }
    }

    int r1 = base + rl1;
    int r2 = base + rl2;
#pragma unroll
    for (int nt = 0; nt < 8; nt++) {
        int c0 = nt * 8 + 2 * kc;
        float b0 = shB[c0], b1 = shB[c0 + 1];
        if (r1 < NN) {
            float2 v;
            v.x = fmaxf(d[nt][0] + b0, 0.f);
            v.y = fmaxf(d[nt][1] + b1, 0.f);
            *reinterpret_cast<float2*>(out + (size_t)r1 * 64 + c0) = v;
        }
        if (r2 < NN) {
            float2 v;
            v.x = fmaxf(d[nt][2] + b0, 0.f);
            v.y = fmaxf(d[nt][3] + b1, 0.f);
            *reinterpret_cast<float2*>(out + (size_t)r2 * 64 + c0) = v;
        }
    }
}

// ---------------- host ----------------
extern "C" void kernel_launch(void* const* d_in, const int* in_sizes, int n_in,
                              void* d_out, int out_size) {
    (void)n_in; (void)out_size;
    const float* x = (const float*)d_in[0];

    int eb, wb;
    if (in_sizes[1] == 2 * NE) { eb = 1; wb = 10; }
    else                        { wb = 1; eb = 14; }

    const int* E[9];
    for (int i = 0; i < 9; i++) E[i] = (const int*)d_in[eb + i];
    const float* W0n = (const float*)d_in[wb + 0];
    const float* W0r = (const float*)d_in[wb + 1];
    const float* b0  = (const float*)d_in[wb + 2];
    const float* W1n = (const float*)d_in[wb + 3];
    const float* W1r = (const float*)d_in[wb + 4];
    const float* b1  = (const float*)d_in[wb + 5];
    const float* P1  = (const float*)d_in[wb + 6];
    const float* pb1 = (const float*)d_in[wb + 7];
    const float* W2n = (const float*)d_in[wb + 8];
    const float* W2r = (const float*)d_in[wb + 9];
    const float* b2  = (const float*)d_in[wb + 10];
    const float* P2  = (const float*)d_in[wb + 11];
    const float* pb2 = (const float*)d_in[wb + 12];

    float *msg0, *xp, *h0, *h1, *Wc0, *Wc1, *W2hi, *W2lo, *bc0, *bc1, *bc2;
    int *hist;
    __half *msg2h, *msg1h, *h0h, *h1h;
    cudaGetSymbolAddress((void**)&msg2h, g_msg2h);
    cudaGetSymbolAddress((void**)&msg1h, g_msg1h);
    cudaGetSymbolAddress((void**)&msg0, g_msg0);
    cudaGetSymbolAddress((void**)&xp,   g_xp);
    cudaGetSymbolAddress((void**)&hist, g_hist);
    cudaGetSymbolAddress((void**)&h0,   g_h0);
    cudaGetSymbolAddress((void**)&h0h,  g_h0h);
    cudaGetSymbolAddress((void**)&h1,   g_h1);
    cudaGetSymbolAddress((void**)&h1h,  g_h1h);
    cudaGetSymbolAddress((void**)&Wc0,  g_Wc0);
    cudaGetSymbolAddress((void**)&Wc1,  g_Wc1);
    cudaGetSymbolAddress((void**)&W2hi, g_W2hi);
    cudaGetSymbolAddress((void**)&W2lo, g_W2lo);
    cudaGetSymbolAddress((void**)&bc0,  g_bc0);
    cudaGetSymbolAddress((void**)&bc1,  g_bc1);
    cudaGetSymbolAddress((void**)&bc2,  g_bc2);

    ESet es01 = {}, es2 = {};
    es01.e[0] = E[0]; es01.e[1] = E[1];
    for (int r = 0; r < 7; r++) es2.e[r] = E[2 + r];

    k_zero_prep<<<2048, 256>>>(x, W0n, W0r, b0, W1n, W1r, b1, P1, pb1, W2n, W2r, b2, P2, pb2);

    // layer-2 binning (independent of layers 0/1 data; only needs edges + hist zero)
    k_hist<<<dim3(NE / 256, 7), 256>>>(es2);
    k_scan1<<<SCAN_NB, 256>>>();
    k_scan2<<<1, 32>>>();
    k_scan3<<<SCAN_NB, 256>>>();
    k_reorder<<<dim3(NE / 256, 7), 256>>>(es2);

    // ---- layer 0 ----
    k_scatter6p<<<dim3(NE / 256, 2), 256>>>(es01, xp, msg0);
    k_gemm0<<<(NN + 255) / 256, 256>>>(msg0, xp, Wc0, bc0, h0, h0h);

    // ---- layer 1 ----
    k_scatter16h<<<dim3(NE / 256, 2), 256>>>(es01, h0h, msg1h);
    k_gemm1<<<(NN + 255) / 256, 256>>>(msg1h, h0, Wc1, bc1, h1, h1h);

    // ---- layer 2: sorted gather-reduce, then tensor-core GEMM ----
    k_accum<<<dim3(NN / 8, 7), 256>>>(h1h, msg2h);
    k_gemm2_tc<<<(NN + 127) / 128, 256>>>(msg2h, h1, hist, W2hi, W2lo, bc2, (float*)d_out);
}

// round 17
// speedup vs baseline: 1.5093x; 1.5093x over previous
#include <cuda_runtime.h>
#include <cuda_fp16.h>

#define NN 100000
#define NE 800000

// ---------------- scratch (static __device__ globals; no allocs) ----------------
__device__ __align__(16) __half g_msg2h[7 * NN * 32];  // 44.8 MB fp16 messages
__device__ __align__(16) __half g_msg1h[2 * NN * 16];  // 6.4 MB fp16 messages
__device__ __align__(16) float g_msg0[2 * NN * 8];     // padded rows: 6 used + 2 pad
__device__ __align__(16) float g_xp  [NN * 8];         // padded x copy (6 used + 2 zero)
__device__ __align__(16) float g_cnt [3 * NN];
__device__ __align__(16) float g_h0  [NN * 16];
__device__ __align__(16) __half g_h0h[NN * 16];        // fp16 copy for layer-1 gather
__device__ __align__(16) float g_h1  [NN * 32];
__device__ __align__(16) __half g_h1h[NN * 32];        // fp16 copy for layer-2 gather
__device__ __align__(16) float g_Wc0[3 * 6 * 16];
__device__ __align__(16) float g_Wc1[3 * 16 * 32];
__device__ __align__(16) float g_W2hi[8 * 64 * 32];    // [ch][n][k], tf32-exact
__device__ __align__(16) float g_W2lo[8 * 64 * 32];
__device__ __align__(16) float g_bc0[16];
__device__ __align__(16) float g_bc1[32];
__device__ __align__(16) float g_bc2[64];

// ---------------- helpers ----------------
__device__ __forceinline__ void red_add_v4(float* a, float4 v) {
    asm volatile("red.global.add.v4.f32 [%0], {%1,%2,%3,%4};"
                 :: "l"(a), "f"(v.x), "f"(v.y), "f"(v.z), "f"(v.w) : "memory");
}
__device__ __forceinline__ void red_add_f(float* a, float v) {
    asm volatile("red.global.add.f32 [%0], %1;" :: "l"(a), "f"(v) : "memory");
}
// 16B of packed halves (8 halves) reduced in one lane-op (max RED width: 128 bits)
__device__ __forceinline__ void red_add_v4h(__half* a, float4 bits) {
    asm volatile("red.global.add.noftz.v4.f16x2 [%0], {%1,%2,%3,%4};"
                 :: "l"(a), "r"(__float_as_uint(bits.x)), "r"(__float_as_uint(bits.y)),
                    "r"(__float_as_uint(bits.z)), "r"(__float_as_uint(bits.w)) : "memory");
}
__device__ __forceinline__ unsigned tf32_of(float f) {
    unsigned r;
    asm("cvt.rna.tf32.f32 %0, %1;" : "=r"(r) : "f"(f));
    return r;
}
__device__ __forceinline__ void mma_tf32(float* d, unsigned a0, unsigned a1,
                                         unsigned a2, unsigned a3,
                                         unsigned b0, unsigned b1) {
    asm("mma.sync.aligned.m16n8k8.row.col.f32.tf32.tf32.f32 "
        "{%0,%1,%2,%3}, {%4,%5,%6,%7}, {%8,%9}, {%0,%1,%2,%3};"
        : "+f"(d[0]), "+f"(d[1]), "+f"(d[2]), "+f"(d[3])
        : "r"(a0), "r"(a1), "r"(a2), "r"(a3), "r"(b0), "r"(b1));
}

struct ESet { const int* e[7]; float* cnt[7]; };

// ---------------- zero scratch + fold weights + pad x (one launch) ----------------
__global__ void k_zero_prep(const float* __restrict__ x,
                            const float* __restrict__ W0n, const float* __restrict__ W0r,
                            const float* __restrict__ b0,
                            const float* __restrict__ W1n, const float* __restrict__ W1r,
                            const float* __restrict__ b1,  const float* __restrict__ P1,
                            const float* __restrict__ pb1,
                            const float* __restrict__ W2n, const float* __restrict__ W2r,
                            const float* __restrict__ b2,  const float* __restrict__ P2,
                            const float* __restrict__ pb2) {
    int i = blockIdx.x * blockDim.x + threadIdx.x;
    int stride = gridDim.x * blockDim.x;
    // ---- weight folding (low thread ids) ----
    if (i < 192) g_Wc0[i] = W0n[i];
    if (i < 96)  g_Wc0[192 + i] = W0r[i] + W0r[96 + i];
    if (i < 16)  g_bc0[i] = b0[i] + b0[16 + i];
    if (i < 1024) g_Wc1[i] = W1n[i];
    if (i < 512)  g_Wc1[1024 + i] = W1r[i] + W1r[512 + i] + P1[i];
    if (i < 32)   g_bc1[i] = b1[i] + b1[32 + i] + pb1[i];
    if (i < 16384) {
        int ch = i >> 11, j = i & 2047;
        int k = j >> 6, n = j & 63;
        float w;
        if (ch < 7) w = W2n[i];
        else {
            w = P2[j];
            for (int r = 0; r < 7; r++) w += W2r[r * 2048 + j];
        }
        unsigned hi = tf32_of(w);
        unsigned lo = tf32_of(w - __uint_as_float(hi));
        int o = ch * 2048 + n * 32 + k;
        g_W2hi[o] = __uint_as_float(hi);
        g_W2lo[o] = __uint_as_float(lo);
    }
    if (i < 64) {
        float s = pb2[i];
        for (int r = 0; r < 7; r++) s += b2[r * 64 + i];
        g_bc2[i] = s;
    }
    // ---- padded x copy ----
    for (int t = i; t < NN * 8; t += stride) {
        int node = t >> 3, c = t & 7;
        g_xp[t] = (c < 6) ? __ldg(x + node * 6 + c) : 0.f;
    }
    // ---- zeroing (grid-stride) ----
    float4 z = make_float4(0.f, 0.f, 0.f, 0.f);
    float4* a2 = reinterpret_cast<float4*>(g_msg2h);
    for (int t = i; t < 7 * NN * 32 / 8; t += stride) a2[t] = z;
    float4* a1 = reinterpret_cast<float4*>(g_msg1h);
    for (int t = i; t < 2 * NN * 16 / 8; t += stride) a1[t] = z;
    float4* a0 = reinterpret_cast<float4*>(g_msg0);
    for (int t = i; t < 2 * NN * 8 / 4; t += stride) a0[t] = z;
    float4* ac = reinterpret_cast<float4*>(g_cnt);
    for (int t = i; t < 3 * NN / 4; t += stride) ac[t] = z;
}

// ---------------- scatter layer 2: fp16, 4 lanes/edge, v4.f16x2 RED (R7-proven) ----------------
__global__ void __launch_bounds__(256)
k_scatter32h(ESet es, const __half* __restrict__ feat, __half* __restrict__ msg) {
    int lane = threadIdx.x & 31;
    int warp = (blockIdx.x * 256 + threadIdx.x) >> 5;
    int e = warp * 32 + lane;
    int r = blockIdx.y;
    const int* ei = es.e[r];
    int src = __ldg(ei + e);
    int dst = __ldg(ei + NE + e);
    float* cp = es.cnt[r];
    if (cp) red_add_f(cp + dst, 1.0f);
    int sub = lane >> 2;   // edge-within-batch 0..7
    int c   = lane & 3;    // 16B chunk 0..3
#pragma unroll
    for (int j = 0; j < 4; j++) {
        int el = j * 8 + sub;
        int s = __shfl_sync(0xffffffffu, src, el);
        int d = __shfl_sync(0xffffffffu, dst, el);
        float4 v = __ldg(reinterpret_cast<const float4*>(feat + (size_t)s * 32) + c);
        red_add_v4h(msg + ((size_t)r * NN + d) * 32 + 8 * c, v);
    }
}

// ---------------- scatter layer 1: fp16, warp-coop 2 lanes/edge (coalesced lines) ----------------
__global__ void __launch_bounds__(256)
k_scatter16h(ESet es, const __half* __restrict__ feat, __half* __restrict__ msg) {
    int lane = threadIdx.x & 31;
    int warp = (blockIdx.x * 256 + threadIdx.x) >> 5;
    int e = warp * 32 + lane;
    int r = blockIdx.y;
    const int* ei = es.e[r];
    int src = __ldg(ei + e);
    int dst = __ldg(ei + NE + e);
    int sub = lane >> 1;   // edge-within-batch 0..15
    int c   = lane & 1;    // 16B chunk 0..1
#pragma unroll
    for (int j = 0; j < 2; j++) {
        int el = j * 16 + sub;
        int s = __shfl_sync(0xffffffffu, src, el);
        int d = __shfl_sync(0xffffffffu, dst, el);
        float4 v = __ldg(reinterpret_cast<const float4*>(feat + (size_t)s * 16) + c);
        red_add_v4h(msg + ((size_t)r * NN + d) * 16 + 8 * c, v);
    }
}

// ---------------- scatter layer 0: f32 padded rows, warp-coop 2 lanes/edge ----------------
// xp rows are 8 floats (cols 6,7 zero); pad columns accumulate zeros into msg0 pad.
__global__ void __launch_bounds__(256)
k_scatter6p(ESet es, const float* __restrict__ xp, float* __restrict__ msg) {
    int lane = threadIdx.x & 31;
    int warp = (blockIdx.x * 256 + threadIdx.x) >> 5;
    int e = warp * 32 + lane;
    int r = blockIdx.y;
    const int* ei = es.e[r];
    int src = __ldg(ei + e);
    int dst = __ldg(ei + NE + e);
    int sub = lane >> 1;   // edge-within-batch 0..15
    int c   = lane & 1;    // 16B chunk 0..1
#pragma unroll
    for (int j = 0; j < 2; j++) {
        int el = j * 16 + sub;
        int s = __shfl_sync(0xffffffffu, src, el);
        int d = __shfl_sync(0xffffffffu, dst, el);
        float4 v = __ldg(reinterpret_cast<const float4*>(xp + (size_t)s * 8) + c);
        red_add_v4(msg + ((size_t)r * NN + d) * 8 + 4 * c, v);
    }
}

// ---------------- layer-0 GEMM: 3 uniform stride-8 f4 channels (msg0 x2, xp) ----------------
// out = msg0[0]@W0 + msg0[1]@W1 + x@Wself + bias; emits h0 + fp16 h0h.
__global__ void __launch_bounds__(256)
k_gemm0(const float* __restrict__ msg0, const float* __restrict__ xp,
        const float* __restrict__ Wcat, const float* __restrict__ bias,
        float* __restrict__ out, __half* __restrict__ hout) {
    constexpr int OUT = 16, LDT = 9;   // 8 payload (6 used) + 1 pad
    __shared__ __align__(16) float shW[6 * OUT];
    __shared__ float shT[256 * LDT];
    int tid  = threadIdx.x;
    int base = blockIdx.x * 256;
    int node = base + tid;

    const float* chp[3] = { msg0, msg0 + (size_t)NN * 8, xp };

    float acc[OUT];
#pragma unroll
    for (int j = 0; j < OUT; j++) acc[j] = __ldg(bias + j);

    float4 pre[2];
    {
        const float4* m4 = reinterpret_cast<const float4*>(chp[0]);
#pragma unroll
        for (int j = 0; j < 2; j++) {
            int f = j * 256 + tid;
            int g = base * 2 + f;
            pre[j] = __ldg(m4 + (g < NN * 2 ? g : NN * 2 - 1));
        }
    }

    for (int ch = 0; ch < 3; ch++) {
        __syncthreads();   // WAR
#pragma unroll
        for (int j = 0; j < 2; j++) {
            int f = j * 256 + tid;
            int nl = f >> 1, c = f & 1;
            float4 v = pre[j];
            float* t = shT + nl * LDT + 4 * c;
            t[0] = v.x; t[1] = v.y; t[2] = v.z; t[3] = v.w;
        }
        if (tid < 96) shW[tid] = __ldg(Wcat + ch * 96 + tid);
        __syncthreads();   // RAW

        if (ch + 1 < 3) {
            const float4* m4 = reinterpret_cast<const float4*>(chp[ch + 1]);
#pragma unroll
            for (int j = 0; j < 2; j++) {
                int f = j * 256 + tid;
                int g = base * 2 + f;
                pre[j] = __ldg(m4 + (g < NN * 2 ? g : NN * 2 - 1));
            }
        }

#pragma unroll
        for (int k = 0; k < 6; k++) {
            float m = shT[tid * LDT + k];
            const float4* w4 = reinterpret_cast<const float4*>(shW + k * OUT);
#pragma unroll
            for (int j = 0; j < OUT / 4; j++) {
                float4 w = w4[j];
                acc[4 * j + 0] += m * w.x;
                acc[4 * j + 1] += m * w.y;
                acc[4 * j + 2] += m * w.z;
                acc[4 * j + 3] += m * w.w;
            }
        }
    }

    if (node < NN) {
        float4* o4 = reinterpret_cast<float4*>(out + (size_t)node * OUT);
        __half2* h2 = reinterpret_cast<__half2*>(hout + (size_t)node * OUT);
#pragma unroll
        for (int j = 0; j < OUT / 4; j++) {
            float4 v;
            v.x = acc[4 * j + 0]; v.y = acc[4 * j + 1];
            v.z = acc[4 * j + 2]; v.w = acc[4 * j + 3];
            o4[j] = v;
            h2[2 * j]     = __floats2half2_rn(v.x, v.y);
            h2[2 * j + 1] = __floats2half2_rn(v.z, v.w);
        }
    }
}

// ---------------- layer-1 GEMM: 2 fp16 msg channels + f32 self, pipelined (R12-proven) ----------------
__global__ void __launch_bounds__(256)
k_gemm1(const __half* __restrict__ msgh, const float* __restrict__ h0,
        const float* __restrict__ Wcat, const float* __restrict__ bias,
        float* __restrict__ out, __half* __restrict__ hout) {
    constexpr int CHUNK = 16, OUT = 32, LDT = CHUNK + 1;
    __shared__ __align__(16) float shW[CHUNK * OUT];
    __shared__ float shT[256 * LDT];
    int tid  = threadIdx.x;
    int base = blockIdx.x * 256;
    int node = base + tid;

    float acc[OUT];
#pragma unroll
    for (int j = 0; j < OUT; j++) acc[j] = __ldg(bias + j);

    float4 pre[4];
    float4 preW[2];
    {
        const float4* src4 = reinterpret_cast<const float4*>(msgh);
#pragma unroll
        for (int j = 0; j < 2; j++) {
            int f = j * 256 + tid;
            int g = base * 2 + f;
            pre[j] = __ldg(src4 + (g < NN * 2 ? g : NN * 2 - 1));
        }
        const float4* w4 = reinterpret_cast<const float4*>(Wcat);
#pragma unroll
        for (int j = 0; j < 2; j++) {
            int f = j * 256 + tid;
            preW[j] = (f < 128) ? __ldg(w4 + f) : make_float4(0.f, 0.f, 0.f, 0.f);
        }
    }

    for (int ch = 0; ch < 3; ch++) {
        __syncthreads();   // WAR
        if (ch < 2) {
#pragma unroll
            for (int j = 0; j < 2; j++) {
                int f = j * 256 + tid;
                int nl = f >> 1, c = f & 1;
                const __half2* hp = reinterpret_cast<const __half2*>(&pre[j]);
                float* t = shT + nl * LDT + 8 * c;
#pragma unroll
                for (int q = 0; q < 4; q++) {
                    float2 f2 = __half22float2(hp[q]);
                    t[2 * q]     = f2.x;
                    t[2 * q + 1] = f2.y;
                }
            }
        } else {
#pragma unroll
            for (int j = 0; j < 4; j++) {
                int f = j * 256 + tid;
                int nl = f >> 2, c = f & 3;
                float4 v = pre[j];
                float* t = shT + nl * LDT + 4 * c;
                t[0] = v.x; t[1] = v.y; t[2] = v.z; t[3] = v.w;
            }
        }
#pragma unroll
        for (int j = 0; j < 2; j++) {
            int f = j * 256 + tid;
            if (f < 128) reinterpret_cast<float4*>(shW)[f] = preW[j];
        }
        __syncthreads();   // RAW

        if (ch + 1 < 3) {
            if (ch + 1 < 2) {
                const float4* src4 = reinterpret_cast<const float4*>(msgh + (size_t)NN * 16);
#pragma unroll
                for (int j = 0; j < 2; j++) {
                    int f = j * 256 + tid;
                    int g = base * 2 + f;
                    pre[j] = __ldg(src4 + (g < NN * 2 ? g : NN * 2 - 1));
                }
            } else {
                const float4* src4 = reinterpret_cast<const float4*>(h0);
#pragma unroll
                for (int j = 0; j < 4; j++) {
                    int f = j * 256 + tid;
                    int g = base * 4 + f;
                    pre[j] = __ldg(src4 + (g < NN * 4 ? g : NN * 4 - 1));
                }
            }
            const float4* w4 = reinterpret_cast<const float4*>(Wcat + (ch + 1) * CHUNK * OUT);
#pragma unroll
            for (int j = 0; j < 2; j++) {
                int f = j * 256 + tid;
                preW[j] = (f < 128) ? __ldg(w4 + f) : make_float4(0.f, 0.f, 0.f, 0.f);
            }
        }

#pragma unroll 8
        for (int k = 0; k < CHUNK; k++) {
            float m = shT[tid * LDT + k];
            const float4* w4 = reinterpret_cast<const float4*>(shW + k * OUT);
#pragma unroll
            for (int j = 0; j < OUT / 4; j++) {
                float4 w = w4[j];
                acc[4 * j + 0] += m * w.x;
                acc[4 * j + 1] += m * w.y;
                acc[4 * j + 2] += m * w.z;
                acc[4 * j + 3] += m * w.w;
            }
        }
    }

    if (node < NN) {
        float4* o4 = reinterpret_cast<float4*>(out + (size_t)node * OUT);
        __half2* h2 = reinterpret_cast<__half2*>(hout + (size_t)node * OUT);
#pragma unroll
        for (int j = 0; j < OUT / 4; j++) {
            float4 v;
            v.x = fmaxf(acc[4 * j + 0], 0.f);
            v.y = fmaxf(acc[4 * j + 1], 0.f);
            v.z = fmaxf(acc[4 * j + 2], 0.f);
            v.w = fmaxf(acc[4 * j + 3], 0.f);
            o4[j] = v;
            h2[2 * j]     = __floats2half2_rn(v.x, v.y);
            h2[2 * j + 1] = __floats2half2_rn(v.z, v.w);
        }
    }
}

// ---------------- layer-2 GEMM: split-tf32 mma.sync, fp16 msg channels (R7-proven) ----------------
__global__ void __launch_bounds__(256)
k_gemm2_tc(const __half* __restrict__ msgh, const float* __restrict__ h1,
           const float* __restrict__ cnt,
           const float* __restrict__ Whi, const float* __restrict__ Wlo,
           const float* __restrict__ bias, float* __restrict__ out) {
    __shared__ float shA [128 * 36];
    __shared__ float shWh[64 * 36];
    __shared__ float shWl[64 * 36];
    __shared__ float shSc[3][128];
    __shared__ float shB[64];
    int tid  = threadIdx.x;
    int lane = tid & 31;
    int w    = tid >> 5;
    int base = blockIdx.x * 128;

    if (tid < 64) shB[tid] = __ldg(bias + tid);
    if (tid < 128) {
        int node = base + tid;
#pragma unroll
        for (int m = 0; m < 3; m++) {
            float c = (node < NN) ? __ldg(cnt + m * NN + node) : 1.f;
            shSc[m][tid] = 1.f / fmaxf(c, 1.f);
        }
    }

    float d[8][4];
#pragma unroll
    for (int nt = 0; nt < 8; nt++)
#pragma unroll
        for (int j = 0; j < 4; j++) d[nt][j] = 0.f;

    float4 pre[4];
    float4 preW[4];
    {
        const float4* src4 = reinterpret_cast<const float4*>(msgh);
#pragma unroll
        for (int j = 0; j < 2; j++) {
            int f = j * 256 + tid;
            int g = base * 4 + f;
            pre[j] = __ldg(src4 + (g < NN * 4 ? g : NN * 4 - 1));
        }
        const float4* wh4 = reinterpret_cast<const float4*>(Whi);
        const float4* wl4 = reinterpret_cast<const float4*>(Wlo);
#pragma unroll
        for (int j = 0; j < 2; j++) preW[j]     = __ldg(wh4 + j * 256 + tid);
#pragma unroll
        for (int j = 0; j < 2; j++) preW[2 + j] = __ldg(wl4 + j * 256 + tid);
    }

    int rl1 = 16 * w + (lane >> 2);
    int rl2 = rl1 + 8;
    int kc  = lane & 3;
    int nb  = lane >> 2;

    for (int ch = 0; ch < 8; ch++) {
        __syncthreads();   // WAR
        int msel = (ch == 2) ? 0 : (ch == 3) ? 1 : (ch == 6) ? 2 : -1;
        if (ch < 7) {
#pragma unroll
            for (int j = 0; j < 2; j++) {
                int f = j * 256 + tid;
                int nl = f >> 2, c4 = f & 3;
                const __half2* hp = reinterpret_cast<const __half2*>(&pre[j]);
                float sc = (msel >= 0) ? shSc[msel][nl] : 1.f;
                float* t = shA + nl * 36 + 8 * c4;
#pragma unroll
                for (int q = 0; q < 4; q++) {
                    float2 f2 = __half22float2(hp[q]);
                    t[2 * q]     = f2.x * sc;
                    t[2 * q + 1] = f2.y * sc;
                }
            }
        } else {
#pragma unroll
            for (int j = 0; j < 4; j++) {
                int f = j * 256 + tid;
                int nl = f >> 3, c4 = f & 7;
                float4 v = pre[j];
                float* t = shA + nl * 36 + 4 * c4;
                t[0] = v.x; t[1] = v.y; t[2] = v.z; t[3] = v.w;
            }
        }
#pragma unroll
        for (int j = 0; j < 2; j++) {
            int f = j * 256 + tid;
            int n = f >> 3, k4 = f & 7;
            float4 vh = preW[j], vl = preW[2 + j];
            float* th = shWh + n * 36 + 4 * k4;
            float* tl = shWl + n * 36 + 4 * k4;
            th[0] = vh.x; th[1] = vh.y; th[2] = vh.z; th[3] = vh.w;
            tl[0] = vl.x; tl[1] = vl.y; tl[2] = vl.z; tl[3] = vl.w;
        }
        __syncthreads();   // RAW

        if (ch + 1 < 8) {
            if (ch + 1 < 7) {
                const float4* src4 = reinterpret_cast<const float4*>(msgh + (size_t)(ch + 1) * NN * 32);
#pragma unroll
                for (int j = 0; j < 2; j++) {
                    int f = j * 256 + tid;
                    int g = base * 4 + f;
                    pre[j] = __ldg(src4 + (g < NN * 4 ? g : NN * 4 - 1));
                }
            } else {
                const float4* src4 = reinterpret_cast<const float4*>(h1);
#pragma unroll
                for (int j = 0; j < 4; j++) {
                    int f = j * 256 + tid;
                    int g = base * 8 + f;
                    pre[j] = __ldg(src4 + (g < NN * 8 ? g : NN * 8 - 1));
                }
            }
            const float4* wh4 = reinterpret_cast<const float4*>(Whi + (ch + 1) * 2048);
            const float4* wl4 = reinterpret_cast<const float4*>(Wlo + (ch + 1) * 2048);
#pragma unroll
            for (int j = 0; j < 2; j++) preW[j]     = __ldg(wh4 + j * 256 + tid);
#pragma unroll
            for (int j = 0; j < 2; j++) preW[2 + j] = __ldg(wl4 + j * 256 + tid);
        }

        bool needLo = (msel >= 0) || (ch == 7);
#pragma unroll
        for (int k0 = 0; k0 < 32; k0 += 8) {
            int c = k0 + kc;
            float a0f = shA[rl1 * 36 + c];
            float a1f = shA[rl2 * 36 + c];
            float a2f = shA[rl1 * 36 + c + 4];
            float a3f = shA[rl2 * 36 + c + 4];
            unsigned ah0 = tf32_of(a0f), ah1 = tf32_of(a1f);
            unsigned ah2 = tf32_of(a2f), ah3 = tf32_of(a3f);
            unsigned al0 = 0, al1 = 0, al2 = 0, al3 = 0;
            if (needLo) {
                al0 = tf32_of(a0f - __uint_as_float(ah0));
                al1 = tf32_of(a1f - __uint_as_float(ah1));
                al2 = tf32_of(a2f - __uint_as_float(ah2));
                al3 = tf32_of(a3f - __uint_as_float(ah3));
            }
#pragma unroll
            for (int nt = 0; nt < 8; nt++) {
                int wr = (nt * 8 + nb) * 36 + k0 + kc;
                unsigned bh0 = __float_as_uint(shWh[wr]);
                unsigned bh1 = __float_as_uint(shWh[wr + 4]);
                unsigned bl0 = __float_as_uint(shWl[wr]);
                unsigned bl1 = __float_as_uint(shWl[wr + 4]);
                mma_tf32(d[nt], ah0, ah1, ah2, ah3, bh0, bh1);
                mma_tf32(d[nt], ah0, ah1, ah2, ah3, bl0, bl1);
                if (needLo) mma_tf32(d[nt], al0, al1, al2, al3, bh0, bh1);
            }
        }
    }

    int r1 = base + rl1;
    int r2 = base + rl2;
#pragma unroll
    for (int nt = 0; nt < 8; nt++) {
        int c0 = nt * 8 + 2 * kc;
        float b0 = shB[c0], b1 = shB[c0 + 1];
        if (r1 < NN) {
            float2 v;
            v.x = fmaxf(d[nt][0] + b0, 0.f);
            v.y = fmaxf(d[nt][1] + b1, 0.f);
            *reinterpret_cast<float2*>(out + (size_t)r1 * 64 + c0) = v;
        }
        if (r2 < NN) {
            float2 v;
            v.x = fmaxf(d[nt][2] + b0, 0.f);
            v.y = fmaxf(d[nt][3] + b1, 0.f);
            *reinterpret_cast<float2*>(out + (size_t)r2 * 64 + c0) = v;
        }
    }
}

// ---------------- host ----------------
extern "C" void kernel_launch(void* const* d_in, const int* in_sizes, int n_in,
                              void* d_out, int out_size) {
    (void)n_in; (void)out_size;
    const float* x = (const float*)d_in[0];

    int eb, wb;
    if (in_sizes[1] == 2 * NE) { eb = 1; wb = 10; }
    else                        { wb = 1; eb = 14; }

    const int* E[9];
    for (int i = 0; i < 9; i++) E[i] = (const int*)d_in[eb + i];
    const float* W0n = (const float*)d_in[wb + 0];
    const float* W0r = (const float*)d_in[wb + 1];
    const float* b0  = (const float*)d_in[wb + 2];
    const float* W1n = (const float*)d_in[wb + 3];
    const float* W1r = (const float*)d_in[wb + 4];
    const float* b1  = (const float*)d_in[wb + 5];
    const float* P1  = (const float*)d_in[wb + 6];
    const float* pb1 = (const float*)d_in[wb + 7];
    const float* W2n = (const float*)d_in[wb + 8];
    const float* W2r = (const float*)d_in[wb + 9];
    const float* b2  = (const float*)d_in[wb + 10];
    const float* P2  = (const float*)d_in[wb + 11];
    const float* pb2 = (const float*)d_in[wb + 12];

    float *msg0, *xp, *cnt, *h0, *h1, *Wc0, *Wc1, *W2hi, *W2lo, *bc0, *bc1, *bc2;
    __half *msg2h, *msg1h, *h0h, *h1h;
    cudaGetSymbolAddress((void**)&msg2h, g_msg2h);
    cudaGetSymbolAddress((void**)&msg1h, g_msg1h);
    cudaGetSymbolAddress((void**)&msg0, g_msg0);
    cudaGetSymbolAddress((void**)&xp,   g_xp);
    cudaGetSymbolAddress((void**)&cnt,  g_cnt);
    cudaGetSymbolAddress((void**)&h0,   g_h0);
    cudaGetSymbolAddress((void**)&h0h,  g_h0h);
    cudaGetSymbolAddress((void**)&h1,   g_h1);
    cudaGetSymbolAddress((void**)&h1h,  g_h1h);
    cudaGetSymbolAddress((void**)&Wc0,  g_Wc0);
    cudaGetSymbolAddress((void**)&Wc1,  g_Wc1);
    cudaGetSymbolAddress((void**)&W2hi, g_W2hi);
    cudaGetSymbolAddress((void**)&W2lo, g_W2lo);
    cudaGetSymbolAddress((void**)&bc0,  g_bc0);
    cudaGetSymbolAddress((void**)&bc1,  g_bc1);
    cudaGetSymbolAddress((void**)&bc2,  g_bc2);

    k_zero_prep<<<2048, 256>>>(x, W0n, W0r, b0, W1n, W1r, b1, P1, pb1, W2n, W2r, b2, P2, pb2);

    // ---- layer 0: x(6) -> h0(16), relations {connected_to, ordered_next}, sum ----
    ESet es01 = {};
    es01.e[0] = E[0]; es01.e[1] = E[1];
    k_scatter6p<<<dim3(NE / 256, 2), 256>>>(es01, xp, msg0);

    k_gemm0<<<(NN + 255) / 256, 256>>>(msg0, xp, Wc0, bc0, h0, h0h);

    // ---- layer 1: h0(16) -> h1(32), same relations, + P1 residual, relu ----
    k_scatter16h<<<dim3(NE / 256, 2), 256>>>(es01, h0h, msg1h);

    k_gemm1<<<(NN + 255) / 256, 256>>>(msg1h, h0, Wc1, bc1, h1, h1h);

    // ---- layer 2: h1(32) -> out(64), 7 relations (mean at 2,3,6), + P2, relu ----
    ESet es2 = {};
    for (int r = 0; r < 7; r++) es2.e[r] = E[2 + r];
    es2.cnt[2] = cnt; es2.cnt[3] = cnt + NN; es2.cnt[6] = cnt + 2 * NN;
    k_scatter32h<<<dim3(NE / 256, 7), 256>>>(es2, h1h, msg2h);

    k_gemm2_tc<<<(NN + 127) / 128, 256>>>(msg2h, h1, cnt, W2hi, W2lo, bc2, (float*)d_out);
}